// round 15
// baseline (speedup 1.0000x reference)
#include <cuda_runtime.h>
#include <cuda_fp16.h>
#include <cstdint>

// NoiseNet: out[e,:] = tanh( concat(nf[recv[e]], nf[send[e]]) @ W + b )
// Factored:  P[n][0:64]  = nf[n] @ W[0:64,:]  + b   (recv table, bias folded)
//            P[n][64:128]= nf[n] @ W[64:128,:]      (send table)
//            out[e]      = tanh( P[recv[e]][0:64] + P[send[e]][64:128] )
// P fp16. Edge kernel: warp = 16 edges, line-coherent gathers, MLP=8 (R14).
// R15: precompute loads A fragments DIRECTLY from gmem (no A smem stage, one
//      fewer barrier); B via smem ldsm; staged coalesced epilogue (R13).

#define D_FEAT 64
#define P_COLS 128
#define MAX_NODES 50000

#define PM 128              // nodes per precompute CTA
#define ROW_B 144           // 64 halfs (128B) + 16B pad: conflict-free LDSM
#define ROW_PS 136          // halfs; staging tile row stride
#define PRE_SMEM (2 * PM * ROW_B)   // Bt + staging overlay

__device__ __half g_P[MAX_NODES * P_COLS];   // 12.8 MB node table (L2-resident)

__device__ __forceinline__ uint32_t smem_u32(const void* p) {
    uint32_t a;
    asm("{ .reg .u64 t; cvta.to.shared.u64 t, %1; cvt.u32.u64 %0, t; }" : "=r"(a) : "l"(p));
    return a;
}
__device__ __forceinline__ float tanh_fast(float x) {
    float y;
    asm("tanh.approx.f32 %0, %1;" : "=f"(y) : "f"(x));
    return y;
}
__device__ __forceinline__ void ldsm_x4(uint32_t& r0, uint32_t& r1,
                                        uint32_t& r2, uint32_t& r3, uint32_t addr) {
    asm volatile("ldmatrix.sync.aligned.m8n8.x4.shared.b16 {%0,%1,%2,%3}, [%4];"
                 : "=r"(r0), "=r"(r1), "=r"(r2), "=r"(r3) : "r"(addr));
}
__device__ __forceinline__ void mma_16x8x16_f16(float c[4], const uint32_t a[4],
                                                uint32_t b0, uint32_t b1) {
    asm volatile(
        "mma.sync.aligned.m16n8k16.row.col.f32.f16.f16.f32 "
        "{%0,%1,%2,%3}, {%4,%5,%6,%7}, {%8,%9}, {%0,%1,%2,%3};"
        : "+f"(c[0]), "+f"(c[1]), "+f"(c[2]), "+f"(c[3])
        : "r"(a[0]), "r"(a[1]), "r"(a[2]), "r"(a[3]), "r"(b0), "r"(b1));
}
__device__ __forceinline__ uint4 ldg_nc_128(const void* p) {
    uint4 v;
    asm volatile("ld.global.nc.v4.u32 {%0,%1,%2,%3}, [%4];"
                 : "=r"(v.x), "=r"(v.y), "=r"(v.z), "=r"(v.w) : "l"(p));
    return v;
}
__device__ __forceinline__ void stg_cs_128(void* p, float4 v) {
    asm volatile("st.global.cs.v4.f32 [%0], {%1,%2,%3,%4};"
                 :: "l"(p), "f"(v.x), "f"(v.y), "f"(v.z), "f"(v.w) : "memory");
}
__device__ __forceinline__ uint32_t pack_h2(float lo, float hi) {
    __half2 h = __floats2half2_rn(lo, hi);
    return *reinterpret_cast<uint32_t*>(&h);
}

// ---- Precompute: P[m0..m0+128][128] = nf @ [Wtop | Wbot] (+bias on cols<64) ----
__global__ __launch_bounds__(256)
void precompute_P_kernel(const float* __restrict__ nf,
                         const float* __restrict__ W,
                         const float* __restrict__ bias,
                         int n_nodes)
{
    extern __shared__ char smem[];
    char* Bt = smem;                               // [128 n][ROW_B] fp16, n-major
    __half* Ps = reinterpret_cast<__half*>(smem);  // staging overlay (post-MMA)

    const int tid = threadIdx.x;
    const int wid = tid >> 5;
    const int lid = tid & 31;
    const int m0  = blockIdx.x * PM;
    const uint32_t bt_addr = smem_u32(Bt);

    // Stage Bt[n][k]: n<64 -> W[k][n]; n>=64 -> W[64+k][n-64]
    for (int c = tid; c < P_COLS * 8; c += 256) {
        const int n  = c >> 3;
        const int kq = c & 7;
        const int off  = (n >= 64) ? 64 : 0;
        const int ncol = n & 63;
        __half2 h[4];
        #pragma unroll
        for (int j = 0; j < 4; j++)
            h[j] = __floats2half2_rn(W[(off + kq * 8 + 2 * j) * 64 + ncol],
                                     W[(off + kq * 8 + 2 * j + 1) * 64 + ncol]);
        *reinterpret_cast<uint4*>(Bt + n * ROW_B + kq * 16)
            = *reinterpret_cast<uint4*>(h);
    }
    __syncthreads();

    // Warp tiling: wm = wid&3 rows 32*wm..+32; wn = wid>>2 cols 64*wn..+64
    const int wm = wid & 3;
    const int wn = wid >> 2;
    const int g  = lid >> 2;
    const int cc = lid & 3;

    float acc[2][8][4];
    #pragma unroll
    for (int mt = 0; mt < 2; mt++)
        #pragma unroll
        for (int nt = 0; nt < 8; nt++)
            #pragma unroll
            for (int r = 0; r < 4; r++)
                acc[mt][nt][r] = 0.0f;

    // A rows for this thread's fragments (clamped; OOB rows are never stored)
    int rowA[2][2];   // [mt][0]: +g, [mt][1]: +g+8
    #pragma unroll
    for (int mt = 0; mt < 2; mt++) {
        int r0 = m0 + wm * 32 + mt * 16 + g;
        int r1 = r0 + 8;
        rowA[mt][0] = (r0 < n_nodes) ? r0 : (n_nodes - 1);
        rowA[mt][1] = (r1 < n_nodes) ? r1 : (n_nodes - 1);
    }

    const int bn_lane = ((lid >> 4) & 1) * 8 + (lid & 7);
    const uint32_t bk16 = (uint32_t)(((lid >> 3) & 1) * 16);

    #pragma unroll
    for (int s = 0; s < 4; s++) {                 // K=64, 16 per step
        const int k0 = s * 16 + 2 * cc;
        const uint32_t koff = (uint32_t)s * 32u;

        // A fragments straight from gmem (f32 -> f16 pack)
        uint32_t a[2][4];
        #pragma unroll
        for (int mt = 0; mt < 2; mt++) {
            const float* p0 = nf + (size_t)rowA[mt][0] * D_FEAT + k0;
            const float* p1 = nf + (size_t)rowA[mt][1] * D_FEAT + k0;
            float2 v0 = *reinterpret_cast<const float2*>(p0);
            float2 v1 = *reinterpret_cast<const float2*>(p1);
            float2 v2 = *reinterpret_cast<const float2*>(p0 + 8);
            float2 v3 = *reinterpret_cast<const float2*>(p1 + 8);
            a[mt][0] = pack_h2(v0.x, v0.y);
            a[mt][1] = pack_h2(v1.x, v1.y);
            a[mt][2] = pack_h2(v2.x, v2.y);
            a[mt][3] = pack_h2(v3.x, v3.y);
        }

        #pragma unroll
        for (int p = 0; p < 4; p++) {
            uint32_t r0, r1, r2, r3;
            const uint32_t bF = bt_addr
                + (uint32_t)((wn * 64 + p * 16 + bn_lane) * ROW_B) + bk16;
            ldsm_x4(r0, r1, r2, r3, bF + koff);
            #pragma unroll
            for (int mt = 0; mt < 2; mt++) {
                mma_16x8x16_f16(acc[mt][2 * p + 0], a[mt], r0, r1);
                mma_16x8x16_f16(acc[mt][2 * p + 1], a[mt], r2, r3);
            }
        }
    }

    // ---- Epilogue pass 1: bias + convert, into SMEM staging tile ----
    __syncthreads();   // Bt fully consumed; safe to overlay Ps
    #pragma unroll
    for (int nt = 0; nt < 8; nt++) {
        const int col = wn * 64 + nt * 8 + 2 * cc;
        float2 bj = make_float2(0.f, 0.f);
        if (col < 64) bj = *reinterpret_cast<const float2*>(&bias[col]);
        #pragma unroll
        for (int mt = 0; mt < 2; mt++) {
            const int row0 = wm * 32 + mt * 16 + g;
            __half2 h0 = __floats2half2_rn(acc[mt][nt][0] + bj.x,
                                           acc[mt][nt][1] + bj.y);
            __half2 h1 = __floats2half2_rn(acc[mt][nt][2] + bj.x,
                                           acc[mt][nt][3] + bj.y);
            *reinterpret_cast<__half2*>(&Ps[row0 * ROW_PS + col]) = h0;
            *reinterpret_cast<__half2*>(&Ps[(row0 + 8) * ROW_PS + col]) = h1;
        }
    }
    __syncthreads();

    // ---- Epilogue pass 2: coalesced 16B stores to g_P ----
    for (int c = tid; c < PM * 16; c += 256) {
        const int r = c >> 4;
        const int q = c & 15;
        const int node = m0 + r;
        if (node < n_nodes) {
            *reinterpret_cast<uint4*>(&g_P[node * P_COLS + q * 8])
                = *reinterpret_cast<const uint4*>(&Ps[r * ROW_PS + q * 8]);
        }
    }
}

// ---- Edge kernel: warp = 16 edges, line-coherent gathers, MLP=8 (R14) ----
__global__ __launch_bounds__(256)
void edge_kernel(const int* __restrict__ senders,
                 const int* __restrict__ receivers,
                 float* __restrict__ out,
                 int n_edges)
{
    const int lane = threadIdx.x & 31;
    const int warp = (blockIdx.x * 256 + threadIdx.x) >> 5;
    const int base = warp * 16;
    if (base >= n_edges) return;

    int idx;
    {
        int e = base + (lane & 15);
        if (e >= n_edges) e = n_edges - 1;
        idx = (lane < 16) ? receivers[e] : senders[e];
    }

    const int g = lane >> 3;
    const int c = lane & 7;
    const int odd = g & 1;                   // 0: recv-carrier, 1: send-carrier
    const int epair = g >> 1;
    const int half_off = odd ? 64 : 0;

    uint4 v[8];
    #pragma unroll
    for (int r = 0; r < 8; r++) {
        const int src = (odd << 4) + 2 * r + epair;
        const int node = __shfl_sync(0xffffffffu, idx, src);
        v[r] = ldg_nc_128(&g_P[node * P_COLS + half_off + c * 8]);
    }

    #pragma unroll
    for (int r = 0; r < 8; r++) {
        const uint32_t s0 = odd ? v[r].x : v[r].z;
        const uint32_t s1 = odd ? v[r].y : v[r].w;
        const uint32_t p0 = __shfl_xor_sync(0xffffffffu, s0, 8);
        const uint32_t p1 = __shfl_xor_sync(0xffffffffu, s1, 8);

        const uint32_t m0 = odd ? v[r].z : v[r].x;
        const uint32_t m1 = odd ? v[r].w : v[r].y;

        const float2 a0 = __half22float2(*reinterpret_cast<const __half2*>(&m0));
        const float2 b0 = __half22float2(*reinterpret_cast<const __half2*>(&p0));
        const float2 a1 = __half22float2(*reinterpret_cast<const __half2*>(&m1));
        const float2 b1 = __half22float2(*reinterpret_cast<const __half2*>(&p1));

        float4 o;
        o.x = tanh_fast(a0.x + b0.x);
        o.y = tanh_fast(a0.y + b0.y);
        o.z = tanh_fast(a1.x + b1.x);
        o.w = tanh_fast(a1.y + b1.y);

        const int e = base + 2 * r + epair;
        if (e < n_edges) {
            float* dst = out + (size_t)e * 64 + c * 8 + (odd ? 4 : 0);
            stg_cs_128(dst, o);
        }
    }
}

extern "C" void kernel_launch(void* const* d_in, const int* in_sizes, int n_in,
                              void* d_out, int out_size)
{
    const float* node_feats = (const float*)d_in[0];
    const int*   senders    = (const int*)d_in[1];
    const int*   receivers  = (const int*)d_in[2];
    const float* W          = (const float*)d_in[3];
    const float* b          = (const float*)d_in[4];
    float*       out        = (float*)d_out;

    const int n_nodes = in_sizes[0] / D_FEAT;
    const int n_edges = in_sizes[1];

    static bool attr_set = false;
    if (!attr_set) {
        cudaFuncSetAttribute(precompute_P_kernel,
                             cudaFuncAttributeMaxDynamicSharedMemorySize, PRE_SMEM);
        attr_set = true;
    }

    const int pre_grid = (n_nodes + PM - 1) / PM;
    precompute_P_kernel<<<pre_grid, 256, PRE_SMEM>>>(node_feats, W, b, n_nodes);

    const int warps_needed = (n_edges + 15) / 16;
    const int edge_grid = (warps_needed + 7) / 8;     // 8 warps per block
    edge_kernel<<<edge_grid, 256>>>(senders, receivers, out, n_edges);
}

// round 16
// speedup vs baseline: 1.0361x; 1.0361x over previous
#include <cuda_runtime.h>
#include <cuda_fp16.h>
#include <cstdint>

// NoiseNet: out[e,:] = tanh( concat(nf[recv[e]], nf[send[e]]) @ W + b )
// Factored:  P[n][0:64]  = nf[n] @ W[0:64,:]  + b   (recv table, bias folded)
//            P[n][64:128]= nf[n] @ W[64:128,:]      (send table)
//            out[e]      = tanh( P[recv[e]][0:64] + P[send[e]][64:128] )
// P fp16. Edge kernel: warp = 16 edges, line-coherent gathers, MLP=8 (R15).
// Precompute: R13 structure (SMEM-staged A, ldsm, staged epilogue) at PM=64
// for finer-grained scheduling (782 CTAs, ~8 CTAs/SM).

#define D_FEAT 64
#define P_COLS 128
#define MAX_NODES 50000

#define PM 64               // nodes per precompute CTA
#define ROW_B 144           // bytes per 64-half row (128B data + 16B pad)
#define ROW_PS 136          // halfs; staging tile row stride (272B)
#define PRE_SMEM (PM * ROW_B + P_COLS * ROW_B)   // A (9216) + Bt (18432) = 27648

__device__ __half g_P[MAX_NODES * P_COLS];   // 12.8 MB node table (L2-resident)

__device__ __forceinline__ uint32_t smem_u32(const void* p) {
    uint32_t a;
    asm("{ .reg .u64 t; cvta.to.shared.u64 t, %1; cvt.u32.u64 %0, t; }" : "=r"(a) : "l"(p));
    return a;
}
__device__ __forceinline__ float tanh_fast(float x) {
    float y;
    asm("tanh.approx.f32 %0, %1;" : "=f"(y) : "f"(x));
    return y;
}
__device__ __forceinline__ void ldsm_x4(uint32_t& r0, uint32_t& r1,
                                        uint32_t& r2, uint32_t& r3, uint32_t addr) {
    asm volatile("ldmatrix.sync.aligned.m8n8.x4.shared.b16 {%0,%1,%2,%3}, [%4];"
                 : "=r"(r0), "=r"(r1), "=r"(r2), "=r"(r3) : "r"(addr));
}
__device__ __forceinline__ void mma_16x8x16_f16(float c[4], const uint32_t a[4],
                                                uint32_t b0, uint32_t b1) {
    asm volatile(
        "mma.sync.aligned.m16n8k16.row.col.f32.f16.f16.f32 "
        "{%0,%1,%2,%3}, {%4,%5,%6,%7}, {%8,%9}, {%0,%1,%2,%3};"
        : "+f"(c[0]), "+f"(c[1]), "+f"(c[2]), "+f"(c[3])
        : "r"(a[0]), "r"(a[1]), "r"(a[2]), "r"(a[3]), "r"(b0), "r"(b1));
}
__device__ __forceinline__ uint4 ldg_nc_128(const void* p) {
    uint4 v;
    asm volatile("ld.global.nc.v4.u32 {%0,%1,%2,%3}, [%4];"
                 : "=r"(v.x), "=r"(v.y), "=r"(v.z), "=r"(v.w) : "l"(p));
    return v;
}
__device__ __forceinline__ void stg_cs_128(void* p, float4 v) {
    asm volatile("st.global.cs.v4.f32 [%0], {%1,%2,%3,%4};"
                 :: "l"(p), "f"(v.x), "f"(v.y), "f"(v.z), "f"(v.w) : "memory");
}

// ---- Precompute: P[m0..m0+64][128] = nf @ [Wtop | Wbot]  (+bias on cols<64) ----
__global__ __launch_bounds__(256)
void precompute_P_kernel(const float* __restrict__ nf,
                         const float* __restrict__ W,
                         const float* __restrict__ bias,
                         int n_nodes)
{
    extern __shared__ char smem[];
    char* As = smem;                    // [64 rows][ROW_B]   fp16 node feats
    char* Bt = smem + PM * ROW_B;       // [128 n][ROW_B]     fp16 Wcat, n-major
    __half* Ps = reinterpret_cast<__half*>(smem);  // staging overlay (post-MMA)

    const int tid = threadIdx.x;
    const int wid = tid >> 5;
    const int lid = tid & 31;
    const int m0  = blockIdx.x * PM;
    const uint32_t a_addr  = smem_u32(As);
    const uint32_t bt_addr = smem_u32(Bt);

    // Stage Bt[n][k]: n<64 -> W[k][n]; n>=64 -> W[64+k][n-64]
    for (int c = tid; c < P_COLS * 8; c += 256) {
        const int n  = c >> 3;
        const int kq = c & 7;
        const int off  = (n >= 64) ? 64 : 0;
        const int ncol = n & 63;
        __half2 h[4];
        #pragma unroll
        for (int j = 0; j < 4; j++)
            h[j] = __floats2half2_rn(W[(off + kq * 8 + 2 * j) * 64 + ncol],
                                     W[(off + kq * 8 + 2 * j + 1) * 64 + ncol]);
        *reinterpret_cast<uint4*>(Bt + n * ROW_B + kq * 16)
            = *reinterpret_cast<uint4*>(h);
    }

    // Stage A: rows = nodes m0..m0+63 (convert f32->f16)
    {
        const float4* nf4 = reinterpret_cast<const float4*>(nf);
        for (int c = tid; c < PM * 8; c += 256) {
            const int r  = c >> 3;
            const int kq = c & 7;
            int node = m0 + r;
            if (node >= n_nodes) node = n_nodes - 1;
            float4 v0 = nf4[node * 16 + kq * 2];
            float4 v1 = nf4[node * 16 + kq * 2 + 1];
            __half2 h[4] = { __floats2half2_rn(v0.x, v0.y),
                             __floats2half2_rn(v0.z, v0.w),
                             __floats2half2_rn(v1.x, v1.y),
                             __floats2half2_rn(v1.z, v1.w) };
            *reinterpret_cast<uint4*>(As + r * ROW_B + kq * 16)
                = *reinterpret_cast<uint4*>(h);
        }
    }
    __syncthreads();

    // Warp tiling: wm = wid&1 -> rows 32*wm..+32; wn = wid>>1 -> cols 32*wn..+32
    const int wm = wid & 1;
    const int wn = wid >> 1;
    const int g  = lid >> 2;
    const int cc = lid & 3;
    const int r16 = lid & 15;
    const int sel = lid >> 4;

    float acc[2][4][4];
    #pragma unroll
    for (int mt = 0; mt < 2; mt++)
        #pragma unroll
        for (int nt = 0; nt < 4; nt++)
            #pragma unroll
            for (int r = 0; r < 4; r++)
                acc[mt][nt][r] = 0.0f;

    uint32_t aOff[2];
    #pragma unroll
    for (int mt = 0; mt < 2; mt++)
        aOff[mt] = (uint32_t)((wm * 32 + mt * 16 + r16) * ROW_B)
                 + (uint32_t)(sel * 16);

    const int bn_lane = ((lid >> 4) & 1) * 8 + (lid & 7);
    const uint32_t bk16 = (uint32_t)(((lid >> 3) & 1) * 16);

    #pragma unroll
    for (int s = 0; s < 4; s++) {                 // K=64, 16 per step
        const uint32_t koff = (uint32_t)s * 32u;
        uint32_t a[2][4];
        #pragma unroll
        for (int mt = 0; mt < 2; mt++)
            ldsm_x4(a[mt][0], a[mt][1], a[mt][2], a[mt][3],
                    a_addr + aOff[mt] + koff);
        #pragma unroll
        for (int p = 0; p < 2; p++) {             // 2 ldsm -> 4 nt frags
            uint32_t r0, r1, r2, r3;
            const uint32_t bF = bt_addr
                + (uint32_t)((wn * 32 + p * 16 + bn_lane) * ROW_B) + bk16;
            ldsm_x4(r0, r1, r2, r3, bF + koff);
            #pragma unroll
            for (int mt = 0; mt < 2; mt++) {
                mma_16x8x16_f16(acc[mt][2 * p + 0], a[mt], r0, r1);
                mma_16x8x16_f16(acc[mt][2 * p + 1], a[mt], r2, r3);
            }
        }
    }

    // ---- Epilogue pass 1: bias + convert, into SMEM staging tile ----
    __syncthreads();   // As/Bt fully consumed; safe to overlay Ps
    #pragma unroll
    for (int nt = 0; nt < 4; nt++) {
        const int col = wn * 32 + nt * 8 + 2 * cc;
        float2 bj = make_float2(0.f, 0.f);
        if (col < 64) bj = *reinterpret_cast<const float2*>(&bias[col]);
        #pragma unroll
        for (int mt = 0; mt < 2; mt++) {
            const int row0 = wm * 32 + mt * 16 + g;
            __half2 h0 = __floats2half2_rn(acc[mt][nt][0] + bj.x,
                                           acc[mt][nt][1] + bj.y);
            __half2 h1 = __floats2half2_rn(acc[mt][nt][2] + bj.x,
                                           acc[mt][nt][3] + bj.y);
            *reinterpret_cast<__half2*>(&Ps[row0 * ROW_PS + col]) = h0;
            *reinterpret_cast<__half2*>(&Ps[(row0 + 8) * ROW_PS + col]) = h1;
        }
    }
    __syncthreads();

    // ---- Epilogue pass 2: coalesced 16B stores to g_P ----
    for (int c = tid; c < PM * 16; c += 256) {
        const int r = c >> 4;
        const int q = c & 15;
        const int node = m0 + r;
        if (node < n_nodes) {
            *reinterpret_cast<uint4*>(&g_P[node * P_COLS + q * 8])
                = *reinterpret_cast<const uint4*>(&Ps[r * ROW_PS + q * 8]);
        }
    }
}

// ---- Edge kernel: warp = 16 edges, line-coherent gathers, MLP=8 (R15) ----
// lanes 0-15: recv idx of edges base+0..15; lanes 16-31: send idx.
// Round r (0..7) serves edges base+2r, base+2r+1.
// Lane groups g=lane>>3: g0 recv(e), g1 send(e), g2 recv(e+1), g3 send(e+1).
__global__ __launch_bounds__(256)
void edge_kernel(const int* __restrict__ senders,
                 const int* __restrict__ receivers,
                 float* __restrict__ out,
                 int n_edges)
{
    const int lane = threadIdx.x & 31;
    const int warp = (blockIdx.x * 256 + threadIdx.x) >> 5;
    const int base = warp * 16;
    if (base >= n_edges) return;

    int idx;
    {
        int e = base + (lane & 15);
        if (e >= n_edges) e = n_edges - 1;
        idx = (lane < 16) ? receivers[e] : senders[e];
    }

    const int g = lane >> 3;
    const int c = lane & 7;
    const int odd = g & 1;                   // 0: recv-carrier, 1: send-carrier
    const int epair = g >> 1;
    const int half_off = odd ? 64 : 0;

    uint4 v[8];
    #pragma unroll
    for (int r = 0; r < 8; r++) {
        const int src = (odd << 4) + 2 * r + epair;
        const int node = __shfl_sync(0xffffffffu, idx, src);
        v[r] = ldg_nc_128(&g_P[node * P_COLS + half_off + c * 8]);
    }

    #pragma unroll
    for (int r = 0; r < 8; r++) {
        const uint32_t s0 = odd ? v[r].x : v[r].z;
        const uint32_t s1 = odd ? v[r].y : v[r].w;
        const uint32_t p0 = __shfl_xor_sync(0xffffffffu, s0, 8);
        const uint32_t p1 = __shfl_xor_sync(0xffffffffu, s1, 8);

        const uint32_t m0 = odd ? v[r].z : v[r].x;
        const uint32_t m1 = odd ? v[r].w : v[r].y;

        const float2 a0 = __half22float2(*reinterpret_cast<const __half2*>(&m0));
        const float2 b0 = __half22float2(*reinterpret_cast<const __half2*>(&p0));
        const float2 a1 = __half22float2(*reinterpret_cast<const __half2*>(&m1));
        const float2 b1 = __half22float2(*reinterpret_cast<const __half2*>(&p1));

        float4 o;
        o.x = tanh_fast(a0.x + b0.x);
        o.y = tanh_fast(a0.y + b0.y);
        o.z = tanh_fast(a1.x + b1.x);
        o.w = tanh_fast(a1.y + b1.y);

        const int e = base + 2 * r + epair;
        if (e < n_edges) {
            float* dst = out + (size_t)e * 64 + c * 8 + (odd ? 4 : 0);
            stg_cs_128(dst, o);
        }
    }
}

extern "C" void kernel_launch(void* const* d_in, const int* in_sizes, int n_in,
                              void* d_out, int out_size)
{
    const float* node_feats = (const float*)d_in[0];
    const int*   senders    = (const int*)d_in[1];
    const int*   receivers  = (const int*)d_in[2];
    const float* W          = (const float*)d_in[3];
    const float* b          = (const float*)d_in[4];
    float*       out        = (float*)d_out;

    const int n_nodes = in_sizes[0] / D_FEAT;
    const int n_edges = in_sizes[1];

    static bool attr_set = false;
    if (!attr_set) {
        cudaFuncSetAttribute(precompute_P_kernel,
                             cudaFuncAttributeMaxDynamicSharedMemorySize, PRE_SMEM);
        attr_set = true;
    }

    const int pre_grid = (n_nodes + PM - 1) / PM;
    precompute_P_kernel<<<pre_grid, 256, PRE_SMEM>>>(node_feats, W, b, n_nodes);

    const int warps_needed = (n_edges + 15) / 16;
    const int edge_grid = (warps_needed + 7) / 8;     // 8 warps per block
    edge_kernel<<<edge_grid, 256>>>(senders, receivers, out, n_edges);
}

// round 17
// speedup vs baseline: 1.1324x; 1.0929x over previous
#include <cuda_runtime.h>
#include <cuda_fp16.h>
#include <cstdint>

// NoiseNet: out[e,:] = tanh( concat(nf[recv[e]], nf[send[e]]) @ W + b )
// Factored:  P[n][0:64]  = nf[n] @ W[0:64,:]  + b   (recv table, bias folded)
//            P[n][64:128]= nf[n] @ W[64:128,:]      (send table)
//            out[e]      = tanh( P[recv[e]][0:64] + P[send[e]][64:128] )
// P fp16. 3 kernels: (1) one-shot W transpose -> g_Bt fp16 [128n][64k],
// (2) precompute GEMM (R13 shape, PM=128, coalesced Bt staging),
// (3) edge kernel: warp = 16 edges, line-coherent gathers, MLP=8 (R15).

#define D_FEAT 64
#define P_COLS 128
#define MAX_NODES 50000

#define PM 128              // nodes per precompute CTA
#define ROW_B 144           // bytes per 64-half row (128B data + 16B pad)
#define ROW_PS 136          // halfs; staging tile row stride (272B)
#define PRE_SMEM (2 * PM * ROW_B)   // A + Bt = 36864; staging overlay fits

__device__ __half g_P[MAX_NODES * P_COLS];   // 12.8 MB node table (L2-resident)
__device__ __half g_Bt[P_COLS * D_FEAT];     // W transposed+concat, fp16, n-major

__device__ __forceinline__ uint32_t smem_u32(const void* p) {
    uint32_t a;
    asm("{ .reg .u64 t; cvta.to.shared.u64 t, %1; cvt.u32.u64 %0, t; }" : "=r"(a) : "l"(p));
    return a;
}
__device__ __forceinline__ float tanh_fast(float x) {
    float y;
    asm("tanh.approx.f32 %0, %1;" : "=f"(y) : "f"(x));
    return y;
}
__device__ __forceinline__ void ldsm_x4(uint32_t& r0, uint32_t& r1,
                                        uint32_t& r2, uint32_t& r3, uint32_t addr) {
    asm volatile("ldmatrix.sync.aligned.m8n8.x4.shared.b16 {%0,%1,%2,%3}, [%4];"
                 : "=r"(r0), "=r"(r1), "=r"(r2), "=r"(r3) : "r"(addr));
}
__device__ __forceinline__ void mma_16x8x16_f16(float c[4], const uint32_t a[4],
                                                uint32_t b0, uint32_t b1) {
    asm volatile(
        "mma.sync.aligned.m16n8k16.row.col.f32.f16.f16.f32 "
        "{%0,%1,%2,%3}, {%4,%5,%6,%7}, {%8,%9}, {%0,%1,%2,%3};"
        : "+f"(c[0]), "+f"(c[1]), "+f"(c[2]), "+f"(c[3])
        : "r"(a[0]), "r"(a[1]), "r"(a[2]), "r"(a[3]), "r"(b0), "r"(b1));
}
__device__ __forceinline__ uint4 ldg_nc_128(const void* p) {
    uint4 v;
    asm volatile("ld.global.nc.v4.u32 {%0,%1,%2,%3}, [%4];"
                 : "=r"(v.x), "=r"(v.y), "=r"(v.z), "=r"(v.w) : "l"(p));
    return v;
}
__device__ __forceinline__ void stg_cs_128(void* p, float4 v) {
    asm volatile("st.global.cs.v4.f32 [%0], {%1,%2,%3,%4};"
                 :: "l"(p), "f"(v.x), "f"(v.y), "f"(v.z), "f"(v.w) : "memory");
}

// ---- One-shot: g_Bt[n][k] = fp16( n<64 ? W[k][n] : W[64+k][n-64] ) ----
__global__ void transpose_W_kernel(const float* __restrict__ W) {
    const int t = blockIdx.x * 256 + threadIdx.x;   // 0..8191
    if (t < P_COLS * D_FEAT) {
        const int n = t >> 6;
        const int k = t & 63;
        const int off  = (n >= 64) ? 64 : 0;
        const int ncol = n & 63;
        g_Bt[t] = __float2half_rn(W[(off + k) * 64 + ncol]);
    }
}

// ---- Precompute: P[m0..m0+128][128] = nf @ [Wtop | Wbot] (+bias on cols<64) ----
__global__ __launch_bounds__(256)
void precompute_P_kernel(const float* __restrict__ nf,
                         const float* __restrict__ bias,
                         int n_nodes)
{
    extern __shared__ char smem[];
    char* As = smem;                    // [128 rows][ROW_B]  fp16 node feats
    char* Bt = smem + PM * ROW_B;       // [128 n][ROW_B]     fp16 Wcat, n-major
    __half* Ps = reinterpret_cast<__half*>(smem);  // staging overlay (post-MMA)

    const int tid = threadIdx.x;
    const int wid = tid >> 5;
    const int lid = tid & 31;
    const int m0  = blockIdx.x * PM;
    const uint32_t a_addr  = smem_u32(As);
    const uint32_t bt_addr = smem_u32(Bt);

    // Stage Bt from pre-transposed g_Bt: coalesced uint4 copies
    {
        const char* src = reinterpret_cast<const char*>(g_Bt);
        #pragma unroll
        for (int c = tid; c < P_COLS * 8; c += 256) {
            const int n  = c >> 3;
            const int kq = c & 7;
            *reinterpret_cast<uint4*>(Bt + n * ROW_B + kq * 16)
                = *reinterpret_cast<const uint4*>(src + n * 128 + kq * 16);
        }
    }

    // Stage A: rows = nodes m0..m0+127 (convert f32->f16)
    {
        const float4* nf4 = reinterpret_cast<const float4*>(nf);
        #pragma unroll
        for (int c = tid; c < PM * 8; c += 256) {
            const int r  = c >> 3;
            const int kq = c & 7;
            int node = m0 + r;
            if (node >= n_nodes) node = n_nodes - 1;
            float4 v0 = nf4[node * 16 + kq * 2];
            float4 v1 = nf4[node * 16 + kq * 2 + 1];
            __half2 h[4] = { __floats2half2_rn(v0.x, v0.y),
                             __floats2half2_rn(v0.z, v0.w),
                             __floats2half2_rn(v1.x, v1.y),
                             __floats2half2_rn(v1.z, v1.w) };
            *reinterpret_cast<uint4*>(As + r * ROW_B + kq * 16)
                = *reinterpret_cast<uint4*>(h);
        }
    }
    __syncthreads();

    // Warp tiling: wm = wid&3 rows 32*wm..+32; wn = wid>>2 cols 64*wn..+64
    const int wm = wid & 3;
    const int wn = wid >> 2;
    const int g  = lid >> 2;
    const int cc = lid & 3;
    const int r16 = lid & 15;
    const int sel = lid >> 4;

    float acc[2][8][4];
    #pragma unroll
    for (int mt = 0; mt < 2; mt++)
        #pragma unroll
        for (int nt = 0; nt < 8; nt++)
            #pragma unroll
            for (int r = 0; r < 4; r++)
                acc[mt][nt][r] = 0.0f;

    uint32_t aOff[2];
    #pragma unroll
    for (int mt = 0; mt < 2; mt++)
        aOff[mt] = (uint32_t)((wm * 32 + mt * 16 + r16) * ROW_B)
                 + (uint32_t)(sel * 16);

    const int bn_lane = ((lid >> 4) & 1) * 8 + (lid & 7);
    const uint32_t bk16 = (uint32_t)(((lid >> 3) & 1) * 16);

    #pragma unroll
    for (int s = 0; s < 4; s++) {                 // K=64, 16 per step
        const uint32_t koff = (uint32_t)s * 32u;
        uint32_t a[2][4];
        #pragma unroll
        for (int mt = 0; mt < 2; mt++)
            ldsm_x4(a[mt][0], a[mt][1], a[mt][2], a[mt][3],
                    a_addr + aOff[mt] + koff);
        #pragma unroll
        for (int p = 0; p < 4; p++) {             // 4 ldsm -> 8 nt frags
            uint32_t r0, r1, r2, r3;
            const uint32_t bF = bt_addr
                + (uint32_t)((wn * 64 + p * 16 + bn_lane) * ROW_B) + bk16;
            ldsm_x4(r0, r1, r2, r3, bF + koff);
            #pragma unroll
            for (int mt = 0; mt < 2; mt++) {
                mma_16x8x16_f16(acc[mt][2 * p + 0], a[mt], r0, r1);
                mma_16x8x16_f16(acc[mt][2 * p + 1], a[mt], r2, r3);
            }
        }
    }

    // ---- Epilogue pass 1: bias + convert, into SMEM staging tile ----
    __syncthreads();   // As/Bt fully consumed; safe to overlay Ps
    #pragma unroll
    for (int nt = 0; nt < 8; nt++) {
        const int col = wn * 64 + nt * 8 + 2 * cc;
        float2 bj = make_float2(0.f, 0.f);
        if (col < 64) bj = *reinterpret_cast<const float2*>(&bias[col]);
        #pragma unroll
        for (int mt = 0; mt < 2; mt++) {
            const int row0 = wm * 32 + mt * 16 + g;
            __half2 h0 = __floats2half2_rn(acc[mt][nt][0] + bj.x,
                                           acc[mt][nt][1] + bj.y);
            __half2 h1 = __floats2half2_rn(acc[mt][nt][2] + bj.x,
                                           acc[mt][nt][3] + bj.y);
            *reinterpret_cast<__half2*>(&Ps[row0 * ROW_PS + col]) = h0;
            *reinterpret_cast<__half2*>(&Ps[(row0 + 8) * ROW_PS + col]) = h1;
        }
    }
    __syncthreads();

    // ---- Epilogue pass 2: coalesced 16B stores to g_P ----
    #pragma unroll
    for (int c = tid; c < PM * 16; c += 256) {
        const int r = c >> 4;
        const int q = c & 15;
        const int node = m0 + r;
        if (node < n_nodes) {
            *reinterpret_cast<uint4*>(&g_P[node * P_COLS + q * 8])
                = *reinterpret_cast<const uint4*>(&Ps[r * ROW_PS + q * 8]);
        }
    }
}

// ---- Edge kernel: warp = 16 edges, line-coherent gathers, MLP=8 (R15) ----
// lanes 0-15: recv idx of edges base+0..15; lanes 16-31: send idx.
// Round r (0..7) serves edges base+2r, base+2r+1.
// Lane groups g=lane>>3: g0 recv(e), g1 send(e), g2 recv(e+1), g3 send(e+1).
__global__ __launch_bounds__(256)
void edge_kernel(const int* __restrict__ senders,
                 const int* __restrict__ receivers,
                 float* __restrict__ out,
                 int n_edges)
{
    const int lane = threadIdx.x & 31;
    const int warp = (blockIdx.x * 256 + threadIdx.x) >> 5;
    const int base = warp * 16;
    if (base >= n_edges) return;

    int idx;
    {
        int e = base + (lane & 15);
        if (e >= n_edges) e = n_edges - 1;
        idx = (lane < 16) ? receivers[e] : senders[e];
    }

    const int g = lane >> 3;
    const int c = lane & 7;
    const int odd = g & 1;                   // 0: recv-carrier, 1: send-carrier
    const int epair = g >> 1;
    const int half_off = odd ? 64 : 0;

    uint4 v[8];
    #pragma unroll
    for (int r = 0; r < 8; r++) {
        const int src = (odd << 4) + 2 * r + epair;
        const int node = __shfl_sync(0xffffffffu, idx, src);
        v[r] = ldg_nc_128(&g_P[node * P_COLS + half_off + c * 8]);
    }

    #pragma unroll
    for (int r = 0; r < 8; r++) {
        const uint32_t s0 = odd ? v[r].x : v[r].z;
        const uint32_t s1 = odd ? v[r].y : v[r].w;
        const uint32_t p0 = __shfl_xor_sync(0xffffffffu, s0, 8);
        const uint32_t p1 = __shfl_xor_sync(0xffffffffu, s1, 8);

        const uint32_t m0 = odd ? v[r].z : v[r].x;
        const uint32_t m1 = odd ? v[r].w : v[r].y;

        const float2 a0 = __half22float2(*reinterpret_cast<const __half2*>(&m0));
        const float2 b0 = __half22float2(*reinterpret_cast<const __half2*>(&p0));
        const float2 a1 = __half22float2(*reinterpret_cast<const __half2*>(&m1));
        const float2 b1 = __half22float2(*reinterpret_cast<const __half2*>(&p1));

        float4 o;
        o.x = tanh_fast(a0.x + b0.x);
        o.y = tanh_fast(a0.y + b0.y);
        o.z = tanh_fast(a1.x + b1.x);
        o.w = tanh_fast(a1.y + b1.y);

        const int e = base + 2 * r + epair;
        if (e < n_edges) {
            float* dst = out + (size_t)e * 64 + c * 8 + (odd ? 4 : 0);
            stg_cs_128(dst, o);
        }
    }
}

extern "C" void kernel_launch(void* const* d_in, const int* in_sizes, int n_in,
                              void* d_out, int out_size)
{
    const float* node_feats = (const float*)d_in[0];
    const int*   senders    = (const int*)d_in[1];
    const int*   receivers  = (const int*)d_in[2];
    const float* W          = (const float*)d_in[3];
    const float* b          = (const float*)d_in[4];
    float*       out        = (float*)d_out;

    const int n_nodes = in_sizes[0] / D_FEAT;
    const int n_edges = in_sizes[1];

    static bool attr_set = false;
    if (!attr_set) {
        cudaFuncSetAttribute(precompute_P_kernel,
                             cudaFuncAttributeMaxDynamicSharedMemorySize, PRE_SMEM);
        attr_set = true;
    }

    transpose_W_kernel<<<(P_COLS * D_FEAT + 255) / 256, 256>>>(W);

    const int pre_grid = (n_nodes + PM - 1) / PM;
    precompute_P_kernel<<<pre_grid, 256, PRE_SMEM>>>(node_feats, b, n_nodes);

    const int warps_needed = (n_edges + 15) / 16;
    const int edge_grid = (warps_needed + 7) / 8;     // 8 warps per block
    edge_kernel<<<edge_grid, 256>>>(senders, receivers, out, n_edges);
}